// round 5
// baseline (speedup 1.0000x reference)
#include <cuda_runtime.h>
#include <cstdint>

// HashGrid encode: 16 levels, F=2, T=2^19, base_res=16, per_level_scale=2.0,
// smoothstep, 2D. Levels 0..5 dense, 6..15 hashed.
//
// v5 = v4 (94.9us) + incremental stores (acc[32] -> 4 live regs; one STG.128
// per 2 levels, same total store count) + __ldcg for levels>=4 (big tables
// bypass L1 allocation so the 170KB of level 0-3 tables stay L1-resident).
// Gather scheme unchanged: corner-pair float4 merge when x is even.

#define NLEVELS 16
#define LOG2_T 19
#define TSIZE (1u << LOG2_T)
#define PRIME1 2654435761u

__global__ __launch_bounds__(256) void hashgrid_encode_kernel(
    const float2* __restrict__ x,          // [N] points in [-1,1]
    const float2* __restrict__ table,      // [16 * T] float2 entries
    float* __restrict__ out,               // [N, 32]
    int n)
{
    int i = blockIdx.x * blockDim.x + threadIdx.x;
    if (i >= n) return;

    float2 xi = __ldg(&x[i]);
    float x0 = xi.x * 0.5f + 0.5f;
    float x1 = xi.y * 0.5f + 0.5f;

    float4* o4 = reinterpret_cast<float4*>(out + (size_t)i * (2 * NLEVELS));
    float e0 = 0.0f, e1 = 0.0f;   // even-level pair staging

#pragma unroll
    for (int l = 0; l < NLEVELS; ++l) {
        const unsigned res = 16u << l;                 // power of two
        const float scale = (float)(res - 1u);

        float p0 = x0 * scale + 0.5f;
        float p1 = x1 * scale + 0.5f;
        float fl0 = floorf(p0);
        float fl1 = floorf(p1);
        float fr0 = p0 - fl0;
        float fr1 = p1 - fl1;
        unsigned g0 = (unsigned)(int)fl0;
        unsigned g1 = (unsigned)(int)fl1;

        // smoothstep weights
        float w0 = fr0 * fr0 * (3.0f - 2.0f * fr0);
        float w1 = fr1 * fr1 * (3.0f - 2.0f * fr1);

        unsigned i00, i10, i01, i11;
        if (l <= 5) {
            const unsigned mask = (res * res) - 1u;
            unsigned b0 = g0 + g1 * res;
            unsigned b1 = b0 + res;
            i00 = b0 & mask;        i10 = (b0 + 1u) & mask;
            i01 = b1 & mask;        i11 = (b1 + 1u) & mask;
        } else {
            const unsigned hmask = TSIZE - 1u;
            unsigned hy0 = g1 * PRIME1;
            unsigned hy1 = hy0 + PRIME1;
            i00 = (g0 ^ hy0) & hmask;        i10 = ((g0 + 1u) ^ hy0) & hmask;
            i01 = (g0 ^ hy1) & hmask;        i11 = ((g0 + 1u) ^ hy1) & hmask;
        }

        const float2* tl = table + (size_t)l * TSIZE;
        float2 f00, f10, f01, f11;

        if ((g0 & 1u) == 0u) {
            // x even: row corners are adjacent table entries -> one aligned float4.
            const float4* tl4 = reinterpret_cast<const float4*>(tl);
            float4 v0, v1;
            if (l <= 3) {
                v0 = __ldg(tl4 + (i00 >> 1));
                v1 = __ldg(tl4 + (i01 >> 1));
            } else {
                v0 = __ldcg(tl4 + (i00 >> 1));
                v1 = __ldcg(tl4 + (i01 >> 1));
            }
            if (i00 & 1u) { f00 = make_float2(v0.z, v0.w); f10 = make_float2(v0.x, v0.y); }
            else          { f00 = make_float2(v0.x, v0.y); f10 = make_float2(v0.z, v0.w); }
            if (i01 & 1u) { f01 = make_float2(v1.z, v1.w); f11 = make_float2(v1.x, v1.y); }
            else          { f01 = make_float2(v1.x, v1.y); f11 = make_float2(v1.z, v1.w); }
        } else {
            if (l <= 3) {
                f00 = __ldg(tl + i00);
                f10 = __ldg(tl + i10);
                f01 = __ldg(tl + i01);
                f11 = __ldg(tl + i11);
            } else {
                f00 = __ldcg(tl + i00);
                f10 = __ldcg(tl + i10);
                f01 = __ldcg(tl + i01);
                f11 = __ldcg(tl + i11);
            }
        }

        float c00 = (1.0f - w0) * (1.0f - w1);
        float c10 = w0 * (1.0f - w1);
        float c01 = (1.0f - w0) * w1;
        float c11 = w0 * w1;

        float sx = c00 * f00.x + c10 * f10.x + c01 * f01.x + c11 * f11.x;
        float sy = c00 * f00.y + c10 * f10.y + c01 * f01.y + c11 * f11.y;

        if ((l & 1) == 0) {
            e0 = sx; e1 = sy;
        } else {
            // flush levels (l-1, l) as one 16B store
            o4[l >> 1] = make_float4(e0, e1, sx, sy);
        }
    }
}

extern "C" void kernel_launch(void* const* d_in, const int* in_sizes, int n_in,
                              void* d_out, int out_size)
{
    const float2* x     = (const float2*)d_in[0];   // [N,2] float32
    const float2* table = (const float2*)d_in[1];   // [16, T, 2] float32
    float* out          = (float*)d_out;            // [N, 32] float32

    int n = in_sizes[0] / 2;
    int threads = 256;
    int blocks = (n + threads - 1) / threads;
    hashgrid_encode_kernel<<<blocks, threads>>>(x, table, out, n);
}

// round 6
// speedup vs baseline: 1.0612x; 1.0612x over previous
#include <cuda_runtime.h>
#include <cstdint>

// HashGrid encode: 16 levels, F=2, T=2^19, base_res=16, per_level_scale=2.0,
// smoothstep, 2D. Levels 0..5 dense, 6..15 hashed.
//
// v6 = v4 (best, 94.9us: acc-array + corner-pair float4 merge) with ONE change:
// __launch_bounds__(256, 6) -> ptxas targets <=42 regs, occupancy cap 5->6
// CTAs/SM. v5 lesson: do NOT stream stores / squeeze to 32 regs (kills
// cross-level load pipelining); keep the acc array and final store burst.

#define NLEVELS 16
#define LOG2_T 19
#define TSIZE (1u << LOG2_T)
#define PRIME1 2654435761u

__global__ __launch_bounds__(256, 6) void hashgrid_encode_kernel(
    const float2* __restrict__ x,          // [N] points in [-1,1]
    const float2* __restrict__ table,      // [16 * T] float2 entries
    float* __restrict__ out,               // [N, 32]
    int n)
{
    int i = blockIdx.x * blockDim.x + threadIdx.x;
    if (i >= n) return;

    float2 xi = __ldg(&x[i]);
    float x0 = xi.x * 0.5f + 0.5f;
    float x1 = xi.y * 0.5f + 0.5f;

    float acc[2 * NLEVELS];

#pragma unroll
    for (int l = 0; l < NLEVELS; ++l) {
        const unsigned res = 16u << l;                 // power of two
        const float scale = (float)(res - 1u);

        float p0 = x0 * scale + 0.5f;
        float p1 = x1 * scale + 0.5f;
        float fl0 = floorf(p0);
        float fl1 = floorf(p1);
        float fr0 = p0 - fl0;
        float fr1 = p1 - fl1;
        unsigned g0 = (unsigned)(int)fl0;
        unsigned g1 = (unsigned)(int)fl1;

        // smoothstep weights
        float w0 = fr0 * fr0 * (3.0f - 2.0f * fr0);
        float w1 = fr1 * fr1 * (3.0f - 2.0f * fr1);

        unsigned i00, i10, i01, i11;
        if (l <= 5) {
            const unsigned mask = (res * res) - 1u;
            unsigned b0 = g0 + g1 * res;
            unsigned b1 = b0 + res;
            i00 = b0 & mask;        i10 = (b0 + 1u) & mask;
            i01 = b1 & mask;        i11 = (b1 + 1u) & mask;
        } else {
            const unsigned hmask = TSIZE - 1u;
            unsigned hy0 = g1 * PRIME1;
            unsigned hy1 = hy0 + PRIME1;
            i00 = (g0 ^ hy0) & hmask;        i10 = ((g0 + 1u) ^ hy0) & hmask;
            i01 = (g0 ^ hy1) & hmask;        i11 = ((g0 + 1u) ^ hy1) & hmask;
        }

        const float2* tl = table + (size_t)l * TSIZE;
        float2 f00, f10, f01, f11;

        if ((g0 & 1u) == 0u) {
            // x even: i10 == i00 ^ 1 and i11 == i01 ^ 1 (hashed: x+1 = x^1;
            // dense: i00,i01 even so +1 stays in the pair, no mask wrap).
            // Each row's two corners are one aligned float4.
            const float4* tl4 = reinterpret_cast<const float4*>(tl);
            float4 v0 = __ldg(tl4 + (i00 >> 1));
            float4 v1 = __ldg(tl4 + (i01 >> 1));
            if (i00 & 1u) { f00 = make_float2(v0.z, v0.w); f10 = make_float2(v0.x, v0.y); }
            else          { f00 = make_float2(v0.x, v0.y); f10 = make_float2(v0.z, v0.w); }
            if (i01 & 1u) { f01 = make_float2(v1.z, v1.w); f11 = make_float2(v1.x, v1.y); }
            else          { f01 = make_float2(v1.x, v1.y); f11 = make_float2(v1.z, v1.w); }
        } else {
            f00 = __ldg(tl + i00);
            f10 = __ldg(tl + i10);
            f01 = __ldg(tl + i01);
            f11 = __ldg(tl + i11);
        }

        float c00 = (1.0f - w0) * (1.0f - w1);
        float c10 = w0 * (1.0f - w1);
        float c01 = (1.0f - w0) * w1;
        float c11 = w0 * w1;

        acc[2 * l]     = c00 * f00.x + c10 * f10.x + c01 * f01.x + c11 * f11.x;
        acc[2 * l + 1] = c00 * f00.y + c10 * f10.y + c01 * f01.y + c11 * f11.y;
    }

    float4* o4 = reinterpret_cast<float4*>(out + (size_t)i * (2 * NLEVELS));
#pragma unroll
    for (int k = 0; k < (2 * NLEVELS) / 4; ++k) {
        o4[k] = make_float4(acc[4 * k], acc[4 * k + 1], acc[4 * k + 2], acc[4 * k + 3]);
    }
}

extern "C" void kernel_launch(void* const* d_in, const int* in_sizes, int n_in,
                              void* d_out, int out_size)
{
    const float2* x     = (const float2*)d_in[0];   // [N,2] float32
    const float2* table = (const float2*)d_in[1];   // [16, T, 2] float32
    float* out          = (float*)d_out;            // [N, 32] float32

    int n = in_sizes[0] / 2;
    int threads = 256;
    int blocks = (n + threads - 1) / threads;
    hashgrid_encode_kernel<<<blocks, threads>>>(x, table, out, n);
}

// round 7
// speedup vs baseline: 1.2957x; 1.2210x over previous
#include <cuda_runtime.h>
#include <cstdint>

// HashGrid encode: 16 levels, F=2, T=2^19, base_res=16, per_level_scale=2.0,
// smoothstep, 2D. Levels 0..5 dense, 6..15 hashed.
//
// v7 = v4 (best, 94.9us) + warp-register transpose for stores.
// v4's stores: 8x STG.128 with lanes 128B apart = 32 lines each = 256
// store wavefronts/warp (8/pt). Here: 5-round shfl.bfly 32x32 in-register
// transpose (no smem!), then 32x STG.32 fully coalesced = 32 wf/warp (1/pt).
// Gather scheme and register structure unchanged (48-reg codegen is the
// proven sweet spot; R2/R3/R5/R6 all lost by disturbing it).

#define NLEVELS 16
#define LOG2_T 19
#define TSIZE (1u << LOG2_T)
#define PRIME1 2654435761u

__global__ __launch_bounds__(256) void hashgrid_encode_kernel(
    const float2* __restrict__ x,          // [N] points in [-1,1]
    const float2* __restrict__ table,      // [16 * T] float2 entries
    float* __restrict__ out,               // [N, 32]
    int n)
{
    const int lane = threadIdx.x & 31;
    int i = blockIdx.x * blockDim.x + threadIdx.x;
    if (i >= n) return;

    float2 xi = __ldg(&x[i]);
    float x0 = xi.x * 0.5f + 0.5f;
    float x1 = xi.y * 0.5f + 0.5f;

    float acc[2 * NLEVELS];

#pragma unroll
    for (int l = 0; l < NLEVELS; ++l) {
        const unsigned res = 16u << l;                 // power of two
        const float scale = (float)(res - 1u);

        float p0 = x0 * scale + 0.5f;
        float p1 = x1 * scale + 0.5f;
        float fl0 = floorf(p0);
        float fl1 = floorf(p1);
        float fr0 = p0 - fl0;
        float fr1 = p1 - fl1;
        unsigned g0 = (unsigned)(int)fl0;
        unsigned g1 = (unsigned)(int)fl1;

        // smoothstep weights
        float w0 = fr0 * fr0 * (3.0f - 2.0f * fr0);
        float w1 = fr1 * fr1 * (3.0f - 2.0f * fr1);

        unsigned i00, i10, i01, i11;
        if (l <= 5) {
            const unsigned mask = (res * res) - 1u;
            unsigned b0 = g0 + g1 * res;
            unsigned b1 = b0 + res;
            i00 = b0 & mask;        i10 = (b0 + 1u) & mask;
            i01 = b1 & mask;        i11 = (b1 + 1u) & mask;
        } else {
            const unsigned hmask = TSIZE - 1u;
            unsigned hy0 = g1 * PRIME1;
            unsigned hy1 = hy0 + PRIME1;
            i00 = (g0 ^ hy0) & hmask;        i10 = ((g0 + 1u) ^ hy0) & hmask;
            i01 = (g0 ^ hy1) & hmask;        i11 = ((g0 + 1u) ^ hy1) & hmask;
        }

        const float2* tl = table + (size_t)l * TSIZE;
        float2 f00, f10, f01, f11;

        if ((g0 & 1u) == 0u) {
            // x even: row corners are adjacent 8B entries -> one aligned float4.
            const float4* tl4 = reinterpret_cast<const float4*>(tl);
            float4 v0 = __ldg(tl4 + (i00 >> 1));
            float4 v1 = __ldg(tl4 + (i01 >> 1));
            if (i00 & 1u) { f00 = make_float2(v0.z, v0.w); f10 = make_float2(v0.x, v0.y); }
            else          { f00 = make_float2(v0.x, v0.y); f10 = make_float2(v0.z, v0.w); }
            if (i01 & 1u) { f01 = make_float2(v1.z, v1.w); f11 = make_float2(v1.x, v1.y); }
            else          { f01 = make_float2(v1.x, v1.y); f11 = make_float2(v1.z, v1.w); }
        } else {
            f00 = __ldg(tl + i00);
            f10 = __ldg(tl + i10);
            f01 = __ldg(tl + i01);
            f11 = __ldg(tl + i11);
        }

        float c00 = (1.0f - w0) * (1.0f - w1);
        float c10 = w0 * (1.0f - w1);
        float c01 = (1.0f - w0) * w1;
        float c11 = w0 * w1;

        acc[2 * l]     = c00 * f00.x + c10 * f10.x + c01 * f01.x + c11 * f11.x;
        acc[2 * l + 1] = c00 * f00.y + c10 * f10.y + c01 * f01.y + c11 * f11.y;
    }

    const int wbase = i & ~31;   // first point of this warp
    if (wbase + 32 <= n) {
        // 32x32 in-register transpose (xor butterfly, 5 rounds).
        // After this, lane L holds acc[p] = channel L of point (wbase+p).
#pragma unroll
        for (int step = 1; step < 32; step <<= 1) {
            const bool up = (lane & step) != 0;
#pragma unroll
            for (int t = 0; t < 32; ++t) {
                if ((t & step) == 0) {
                    float lo = acc[t], hi = acc[t + step];
                    float send = up ? lo : hi;
                    float recv = __shfl_xor_sync(0xffffffffu, send, step);
                    if (up) acc[t] = recv; else acc[t + step] = recv;
                }
            }
        }
        // Fully coalesced: each STG.32 writes 128 consecutive bytes (1 line).
        float* ot = out + (size_t)wbase * 32;
#pragma unroll
        for (int p = 0; p < 32; ++p)
            ot[p * 32 + lane] = acc[p];
    } else {
        // tail warp (not hit for N = 524288): per-thread stores
        float4* o4 = reinterpret_cast<float4*>(out + (size_t)i * 32);
#pragma unroll
        for (int k = 0; k < 8; ++k)
            o4[k] = make_float4(acc[4*k], acc[4*k+1], acc[4*k+2], acc[4*k+3]);
    }
}

extern "C" void kernel_launch(void* const* d_in, const int* in_sizes, int n_in,
                              void* d_out, int out_size)
{
    const float2* x     = (const float2*)d_in[0];   // [N,2] float32
    const float2* table = (const float2*)d_in[1];   // [16, T, 2] float32
    float* out          = (float*)d_out;            // [N, 32] float32

    int n = in_sizes[0] / 2;
    int threads = 256;
    int blocks = (n + threads - 1) / threads;
    hashgrid_encode_kernel<<<blocks, threads>>>(x, table, out, n);
}